// round 1
// baseline (speedup 1.0000x reference)
#include <cuda_runtime.h>
#include <cstdint>

#define ND 128
#define ED 64
#define NH 4
#define HD 32
#define MAX_NODES 50000
#define MAX_EDGES 600000

// ---------------- scratch (static device globals; no allocs allowed) -------
__device__ __align__(16) float g_h[MAX_NODES * ND];      // projected nodes
__device__ __align__(16) float g_s1[MAX_NODES * NH];     // h . a[:, 0:32]
__device__ __align__(16) float g_s2[MAX_NODES * NH];     // h . a[:, 32:64]
__device__ __align__(16) float g_att[MAX_EDGES * NH];    // att, then ex (in place)
__device__ __align__(16) float g_m[MAX_NODES * NH];      // segment max (>=0)
__device__ __align__(16) float g_emn[MAX_NODES * NH];    // exp(-m)
__device__ __align__(16) float g_denom[MAX_NODES * NH];  // softmax denominator
__device__ __align__(16) float g_v[NH * ED];             // folded edge attn vector

// ---------------- kernel: fold W_edge into attention vector ----------------
// v[h][k] = sum_d W_edge[h*HD+d][k] * a[h][2*HD+d]
__global__ void kern_v(const float* __restrict__ W_edge, const float* __restrict__ a) {
    int t = threadIdx.x;            // 256 threads == NH*ED
    int h = t >> 6;
    int k = t & 63;
    float s = 0.f;
#pragma unroll
    for (int d = 0; d < HD; d++)
        s += W_edge[(h * HD + d) * ED + k] * __ldg(&a[h * 3 * HD + 2 * HD + d]);
    g_v[h * ED + k] = s;
}

// ---------------- kernel: zero m -------------------------------------------
__global__ void kern_zero_m(int n) {
    int i = blockIdx.x * blockDim.x + threadIdx.x;
    if (i < n) g_m[i] = 0.f;
}

// ---------------- kernel: h = X @ W_node^T (fp32 tiled GEMM) ---------------
// 256 threads, 64 nodes x 128 cols per block. W transposed in smem.
__global__ void kern_gemm(const float* __restrict__ X, const float* __restrict__ W,
                          int n_nodes) {
    extern __shared__ float sm[];
    float(*Ws)[132] = (float(*)[132])sm;               // [128][132] (k-major)
    float(*As)[ND]  = (float(*)[ND])(sm + 128 * 132);  // [64][128]
    int t = threadIdx.x;

    for (int i = t; i < ND * ND; i += 256) {
        int j = i >> 7, k = i & 127;
        Ws[k][j] = W[i];
    }
    int row0 = blockIdx.x * 64;
    for (int i = t; i < 64 * ND; i += 256) {
        int r = i >> 7, k = i & 127;
        int gr = row0 + r;
        As[r][k] = (gr < n_nodes) ? X[(size_t)gr * ND + k] : 0.f;
    }
    __syncthreads();

    int tx = t & 31, ty = t >> 5;  // tx: 32 col-groups of 4, ty: 8 row phases
    float acc[8][4];
#pragma unroll
    for (int rr = 0; rr < 8; rr++)
#pragma unroll
        for (int cc = 0; cc < 4; cc++) acc[rr][cc] = 0.f;

#pragma unroll 4
    for (int k = 0; k < ND; k += 4) {
        float4 w0 = *(const float4*)&Ws[k + 0][tx * 4];
        float4 w1 = *(const float4*)&Ws[k + 1][tx * 4];
        float4 w2 = *(const float4*)&Ws[k + 2][tx * 4];
        float4 w3 = *(const float4*)&Ws[k + 3][tx * 4];
#pragma unroll
        for (int rr = 0; rr < 8; rr++) {
            float4 a4 = *(const float4*)&As[ty + 8 * rr][k];
            acc[rr][0] += a4.x * w0.x + a4.y * w1.x + a4.z * w2.x + a4.w * w3.x;
            acc[rr][1] += a4.x * w0.y + a4.y * w1.y + a4.z * w2.y + a4.w * w3.y;
            acc[rr][2] += a4.x * w0.z + a4.y * w1.z + a4.z * w2.z + a4.w * w3.z;
            acc[rr][3] += a4.x * w0.w + a4.y * w1.w + a4.z * w2.w + a4.w * w3.w;
        }
    }
#pragma unroll
    for (int rr = 0; rr < 8; rr++) {
        int gr = row0 + ty + 8 * rr;
        if (gr < n_nodes) {
            float4 o = make_float4(acc[rr][0], acc[rr][1], acc[rr][2], acc[rr][3]);
            *(float4*)&g_h[(size_t)gr * ND + tx * 4] = o;
        }
    }
}

// ---------------- kernel: per-node s1/s2 (warp per node) -------------------
__global__ void kern_s(const float* __restrict__ a, int n_nodes) {
    int warp = (blockIdx.x * blockDim.x + threadIdx.x) >> 5;
    int lane = threadIdx.x & 31;
    if (warp >= n_nodes) return;
    int head = lane >> 3;
    int off = 4 * (lane & 7);
    float4 hv = *(const float4*)&g_h[(size_t)warp * ND + 4 * lane];
    const float* a1 = &a[head * 3 * HD + off];
    const float* a2 = &a[head * 3 * HD + HD + off];
    float p1 = hv.x * __ldg(a1) + hv.y * __ldg(a1 + 1) + hv.z * __ldg(a1 + 2) + hv.w * __ldg(a1 + 3);
    float p2 = hv.x * __ldg(a2) + hv.y * __ldg(a2 + 1) + hv.z * __ldg(a2 + 2) + hv.w * __ldg(a2 + 3);
#pragma unroll
    for (int o = 4; o >= 1; o >>= 1) {
        p1 += __shfl_down_sync(0xffffffffu, p1, o, 8);
        p2 += __shfl_down_sync(0xffffffffu, p2, o, 8);
    }
    if ((lane & 7) == 0) {
        g_s1[warp * NH + head] = p1;
        g_s2[warp * NH + head] = p2;
    }
}

// ---------------- kernel: edge pass 1 (att + segment max) ------------------
// 16 lanes per edge: coalesced 64-float row read, shfl reduce 4 head-dots.
__global__ void kern_p1(const float* __restrict__ edgef, const int* __restrict__ ei,
                        int n_edges) {
    __shared__ float vs[NH * ED];  // 256 floats
    vs[threadIdx.x] = g_v[threadIdx.x];
    __syncthreads();

    int gid = blockIdx.x * 256 + threadIdx.x;
    int edge = gid >> 4;
    int l = threadIdx.x & 15;
    if (edge >= n_edges) return;

    float4 ef = *(const float4*)&edgef[(size_t)edge * ED + 4 * l];
    float p[NH];
#pragma unroll
    for (int h = 0; h < NH; h++) {
        const float* v = &vs[h * ED + 4 * l];
        p[h] = ef.x * v[0] + ef.y * v[1] + ef.z * v[2] + ef.w * v[3];
    }
#pragma unroll
    for (int o = 8; o >= 1; o >>= 1)
#pragma unroll
        for (int h = 0; h < NH; h++) p[h] += __shfl_down_sync(0xffffffffu, p[h], o, 16);

    if (l == 0) {
        int src = ei[edge];
        int tgt = ei[n_edges + edge];
        float4 s1 = *(const float4*)&g_s1[src * NH];
        float4 s2 = *(const float4*)&g_s2[tgt * NH];
        float att[NH];
        att[0] = s1.x + s2.x + p[0];
        att[1] = s1.y + s2.y + p[1];
        att[2] = s1.z + s2.z + p[2];
        att[3] = s1.w + s2.w + p[3];
        float4 o4;
        o4.x = att[0] > 0.f ? att[0] : 0.2f * att[0];
        o4.y = att[1] > 0.f ? att[1] : 0.2f * att[1];
        o4.z = att[2] > 0.f ? att[2] : 0.2f * att[2];
        o4.w = att[3] > 0.f ? att[3] : 0.2f * att[3];
        *(float4*)&g_att[(size_t)edge * NH] = o4;
        // segment max: m init 0, only positive values can win; nonneg float
        // bits order like ints -> int atomicMax is exact.
        float lk[4] = {o4.x, o4.y, o4.z, o4.w};
#pragma unroll
        for (int h = 0; h < NH; h++)
            if (lk[h] > 0.f)
                atomicMax((int*)&g_m[tgt * NH + h], __float_as_int(lk[h]));
    }
}

// ---------------- kernel: node pass (emn, denom init) ----------------------
__global__ void kern_c(int n, float fE) {
    int i = blockIdx.x * blockDim.x + threadIdx.x;
    if (i < n) {
        float e = expf(-g_m[i]);
        g_emn[i] = e;
        g_denom[i] = fE * e;
    }
}

// ---------------- kernel: edge pass 2 (ex + denom accumulate) --------------
__global__ void kern_p2(const int* __restrict__ ei, int n_edges) {
    int e = blockIdx.x * blockDim.x + threadIdx.x;
    if (e >= n_edges) return;
    int tgt = ei[n_edges + e];
    float4 att = *(const float4*)&g_att[(size_t)e * NH];
    float4 m = *(const float4*)&g_m[tgt * NH];
    float4 emn = *(const float4*)&g_emn[tgt * NH];
    float4 ex;
    ex.x = expf(att.x - m.x);
    ex.y = expf(att.y - m.y);
    ex.z = expf(att.z - m.z);
    ex.w = expf(att.w - m.w);
    *(float4*)&g_att[(size_t)e * NH] = ex;  // att buffer now holds ex
    atomicAdd(&g_denom[tgt * NH + 0], ex.x - emn.x);
    atomicAdd(&g_denom[tgt * NH + 1], ex.y - emn.y);
    atomicAdd(&g_denom[tgt * NH + 2], ex.z - emn.z);
    atomicAdd(&g_denom[tgt * NH + 3], ex.w - emn.w);
}

// ---------------- kernel: edge pass 3 (weighted scatter) -------------------
// warp per edge; lane l covers output floats [4l, 4l+4); head = l>>3.
__global__ void kern_p3(const int* __restrict__ ei, float* __restrict__ out,
                        int n_edges) {
    int e = (blockIdx.x * blockDim.x + threadIdx.x) >> 5;
    int lane = threadIdx.x & 31;
    if (e >= n_edges) return;
    int src = ei[e];
    int tgt = ei[n_edges + e];
    int head = lane >> 3;
    float w = g_att[(size_t)e * NH + head] / g_denom[tgt * NH + head];
    float4 hv = *(const float4*)&g_h[(size_t)src * ND + 4 * lane];
    float4 v = make_float4(w * hv.x, w * hv.y, w * hv.z, w * hv.w);
    float* p = &out[(size_t)tgt * ND + 4 * lane];
    asm volatile("red.global.add.v4.f32 [%0], {%1, %2, %3, %4};" ::"l"(p), "f"(v.x),
                 "f"(v.y), "f"(v.z), "f"(v.w)
                 : "memory");
}

// ---------------- launch ----------------------------------------------------
extern "C" void kernel_launch(void* const* d_in, const int* in_sizes, int n_in,
                              void* d_out, int out_size) {
    const float* nodef = (const float*)d_in[0];
    const int* ei = (const int*)d_in[1];
    const float* edgef = (const float*)d_in[2];
    const float* W_node = (const float*)d_in[3];
    const float* W_edge = (const float*)d_in[4];
    const float* a = (const float*)d_in[5];
    float* out = (float*)d_out;

    int n_nodes = in_sizes[0] / ND;
    int n_edges = in_sizes[1] / 2;

    cudaMemsetAsync(out, 0, (size_t)n_nodes * ND * sizeof(float));

    kern_v<<<1, 256>>>(W_edge, a);
    kern_zero_m<<<(n_nodes * NH + 255) / 256, 256>>>(n_nodes * NH);

    const int gemm_smem = (128 * 132 + 64 * 128) * (int)sizeof(float);  // ~100KB
    cudaFuncSetAttribute(kern_gemm, cudaFuncAttributeMaxDynamicSharedMemorySize,
                         gemm_smem);
    kern_gemm<<<(n_nodes + 63) / 64, 256, gemm_smem>>>(nodef, W_node, n_nodes);

    kern_s<<<(n_nodes + 7) / 8, 256>>>(a, n_nodes);
    kern_p1<<<(n_edges + 15) / 16, 256>>>(edgef, ei, n_edges);
    kern_c<<<(n_nodes * NH + 255) / 256, 256>>>(n_nodes * NH, (float)n_edges);
    kern_p2<<<(n_edges + 255) / 256, 256>>>(ei, n_edges);
    kern_p3<<<(n_edges + 7) / 8, 256>>>(ei, out, n_edges);
}

// round 2
// speedup vs baseline: 1.2450x; 1.2450x over previous
#include <cuda_runtime.h>
#include <cstdint>

#define ND 128
#define ED 64
#define NH 4
#define HD 32
#define MAX_NODES 50000
#define MAX_EDGES 600000

typedef unsigned long long ull;

// ---------------- scratch (static device globals) ---------------------------
__device__ __align__(16) float g_h[MAX_NODES * ND];     // projected nodes
__device__ __align__(16) float g_s1[MAX_NODES * NH];    // h . a[:, 0:32]
__device__ __align__(16) float g_s2[MAX_NODES * NH];    // h . a[:, 32:64]
__device__ __align__(16) float g_att[MAX_EDGES * NH];   // leaky-relu scores
__device__ __align__(16) float g_v[NH * ED];            // folded edge attn vec
__device__ int g_cnt[MAX_NODES + 1];                    // degree histogram
__device__ int g_off[MAX_NODES + 1];                    // CSR row offsets
__device__ int g_head[MAX_NODES];                       // scatter cursors
__device__ int g_csr[MAX_EDGES];                        // edge ids grouped by tgt
__device__ int g_part[64];                              // scan partials

#define FMA2(d, a, b) \
    asm("fma.rn.f32x2 %0, %1, %2, %0;" : "+l"(d) : "l"(a), "l"(b))
#define PACKDUP(d, f) \
    asm("mov.b64 %0, {%1, %1};" : "=l"(d) : "r"(__float_as_uint(f)))

// ---------------- fold W_edge into attention vector -------------------------
__global__ void kern_v(const float* __restrict__ W_edge, const float* __restrict__ a) {
    int t = threadIdx.x;  // 256 == NH*ED
    int h = t >> 6, k = t & 63;
    float s = 0.f;
#pragma unroll
    for (int d = 0; d < HD; d++)
        s += W_edge[(h * HD + d) * ED + k] * __ldg(&a[h * 3 * HD + 2 * HD + d]);
    g_v[h * ED + k] = s;
}

// ---------------- CSR build --------------------------------------------------
__global__ void kern_zero_cnt(int n) {
    int i = blockIdx.x * blockDim.x + threadIdx.x;
    if (i <= n) g_cnt[i] = 0;
}

__global__ void kern_hist(const int* __restrict__ ei, int n_edges) {
    int e = blockIdx.x * blockDim.x + threadIdx.x;
    if (e < n_edges) atomicAdd(&g_cnt[ei[n_edges + e]], 1);
}

__global__ void kern_scan_part(int n) {  // 256 thr x 4 items
    __shared__ int wsum[8];
    int t = threadIdx.x;
    int base = blockIdx.x * 1024 + t * 4;
    int v0 = (base + 0 < n) ? g_cnt[base + 0] : 0;
    int v1 = (base + 1 < n) ? g_cnt[base + 1] : 0;
    int v2 = (base + 2 < n) ? g_cnt[base + 2] : 0;
    int v3 = (base + 3 < n) ? g_cnt[base + 3] : 0;
    int sum = v0 + v1 + v2 + v3;
    int lane = t & 31, w = t >> 5;
    int inc = sum;
#pragma unroll
    for (int o = 1; o < 32; o <<= 1) {
        int x = __shfl_up_sync(0xffffffffu, inc, o);
        if (lane >= o) inc += x;
    }
    if (lane == 31) wsum[w] = inc;
    __syncthreads();
    if (t == 0) {
        int acc = 0;
        for (int i = 0; i < 8; i++) { int x = wsum[i]; wsum[i] = acc; acc += x; }
    }
    __syncthreads();
    int excl = inc - sum + wsum[w];
    if (base + 0 < n) g_off[base + 0] = excl;
    if (base + 1 < n) g_off[base + 1] = excl + v0;
    if (base + 2 < n) g_off[base + 2] = excl + v0 + v1;
    if (base + 3 < n) g_off[base + 3] = excl + v0 + v1 + v2;
    if (t == 255) g_part[blockIdx.x] = excl + sum;
}

__global__ void kern_scan_top(int nb) {  // 1 block, 64 threads
    __shared__ int ws[2];
    int t = threadIdx.x;
    int v = (t < nb) ? g_part[t] : 0;
    int lane = t & 31, w = t >> 5;
    int inc = v;
#pragma unroll
    for (int o = 1; o < 32; o <<= 1) {
        int x = __shfl_up_sync(0xffffffffu, inc, o);
        if (lane >= o) inc += x;
    }
    if (lane == 31) ws[w] = inc;
    __syncthreads();
    int add = (w == 1) ? ws[0] : 0;
    if (t < nb) g_part[t] = inc - v + add;
}

__global__ void kern_scan_add(int n, int n_edges) {
    int i = blockIdx.x * blockDim.x + threadIdx.x;
    if (i < n) {
        int o = g_off[i] + g_part[i >> 10];
        g_off[i] = o;
        g_head[i] = o;
    }
    if (i == 0) g_off[n] = n_edges;
}

__global__ void kern_scatter(const int* __restrict__ ei, int n_edges) {
    int e = blockIdx.x * blockDim.x + threadIdx.x;
    if (e >= n_edges) return;
    int pos = atomicAdd(&g_head[ei[n_edges + e]], 1);
    g_csr[pos] = e;
}

// ---------------- h = X @ W^T (f32x2 GEMM) + fused s1/s2 --------------------
// 256 threads; block tile 64 rows x 128 cols. Thread (tx = t&31, ty = t>>5)
// owns rows ty*8..ty*8+7 (4 packed row-pairs) and cols 4*tx..4*tx+3.
__global__ void kern_gemm(const float* __restrict__ X, const float* __restrict__ W,
                          const float* __restrict__ a, int n) {
    extern __shared__ float sm[];
    float* Ws = sm;                  // [128 k][132 cols]
    float* At = sm + 128 * 132;     // [128 k][66 rows] (k-major rows)
    int t = threadIdx.x;

    for (int i = t; i < ND * ND; i += 256) {
        int j = i >> 7, k = i & 127;
        Ws[k * 132 + j] = W[i];
    }
    int row0 = blockIdx.x * 64;
    for (int i = t; i < 64 * ND; i += 256) {
        int r = i >> 7, k = i & 127;
        int gr = row0 + r;
        At[k * 66 + r] = (gr < n) ? X[(size_t)gr * ND + k] : 0.f;
    }
    __syncthreads();

    int tx = t & 31, ty = t >> 5;
    ull acc[4][4];
#pragma unroll
    for (int p = 0; p < 4; p++)
#pragma unroll
        for (int c = 0; c < 4; c++) acc[p][c] = 0ULL;

    const ull* ab = (const ull*)At + ty * 4;  // + k*33 per step
    const float* wb = &Ws[tx * 4];

#pragma unroll 4
    for (int k = 0; k < ND; k++) {
        float4 wv = *(const float4*)(wb + k * 132);
        ull w0, w1, w2, w3;
        PACKDUP(w0, wv.x); PACKDUP(w1, wv.y); PACKDUP(w2, wv.z); PACKDUP(w3, wv.w);
        ull a0 = ab[k * 33 + 0];
        ull a1 = ab[k * 33 + 1];
        ull a2 = ab[k * 33 + 2];
        ull a3 = ab[k * 33 + 3];
        FMA2(acc[0][0], a0, w0); FMA2(acc[0][1], a0, w1);
        FMA2(acc[0][2], a0, w2); FMA2(acc[0][3], a0, w3);
        FMA2(acc[1][0], a1, w0); FMA2(acc[1][1], a1, w1);
        FMA2(acc[1][2], a1, w2); FMA2(acc[1][3], a1, w3);
        FMA2(acc[2][0], a2, w0); FMA2(acc[2][1], a2, w1);
        FMA2(acc[2][2], a2, w2); FMA2(acc[2][3], a2, w3);
        FMA2(acc[3][0], a3, w0); FMA2(acc[3][1], a3, w1);
        FMA2(acc[3][2], a3, w2); FMA2(acc[3][3], a3, w3);
    }

    // epilogue: store h rows + per-head s1/s2 dots (8-lane group reduce)
    int head = tx >> 3;
    int cbase = head * 3 * HD + ((tx * 4) & 31);
    float4 a1v = *(const float4*)&a[cbase];
    float4 a2v = *(const float4*)&a[cbase + HD];

#pragma unroll
    for (int p = 0; p < 4; p++) {
#pragma unroll
        for (int half = 0; half < 2; half++) {
            union { ull u; float2 f; } c0, c1, c2, c3;
            c0.u = acc[p][0]; c1.u = acc[p][1]; c2.u = acc[p][2]; c3.u = acc[p][3];
            float f0 = half ? c0.f.y : c0.f.x;
            float f1 = half ? c1.f.y : c1.f.x;
            float f2 = half ? c2.f.y : c2.f.x;
            float f3 = half ? c3.f.y : c3.f.x;
            int gr = row0 + ty * 8 + p * 2 + half;
            if (gr < n)
                *(float4*)&g_h[(size_t)gr * ND + tx * 4] = make_float4(f0, f1, f2, f3);
            float d1 = f0 * a1v.x + f1 * a1v.y + f2 * a1v.z + f3 * a1v.w;
            float d2 = f0 * a2v.x + f1 * a2v.y + f2 * a2v.z + f3 * a2v.w;
#pragma unroll
            for (int o = 4; o >= 1; o >>= 1) {
                d1 += __shfl_down_sync(0xffffffffu, d1, o, 8);
                d2 += __shfl_down_sync(0xffffffffu, d2, o, 8);
            }
            if ((tx & 7) == 0 && gr < n) {
                g_s1[gr * NH + head] = d1;
                g_s2[gr * NH + head] = d2;
            }
        }
    }
}

// ---------------- edge pass: att scores --------------------------------------
__global__ void kern_p1(const float* __restrict__ edgef, const int* __restrict__ ei,
                        int n_edges) {
    __shared__ float vs[NH * ED];
    vs[threadIdx.x] = g_v[threadIdx.x];
    __syncthreads();

    int gid = blockIdx.x * 256 + threadIdx.x;
    int edge = gid >> 4;
    int l = threadIdx.x & 15;
    if (edge >= n_edges) return;

    float4 ef = *(const float4*)&edgef[(size_t)edge * ED + 4 * l];
    float p[NH];
#pragma unroll
    for (int h = 0; h < NH; h++) {
        const float* v = &vs[h * ED + 4 * l];
        p[h] = ef.x * v[0] + ef.y * v[1] + ef.z * v[2] + ef.w * v[3];
    }
#pragma unroll
    for (int o = 8; o >= 1; o >>= 1)
#pragma unroll
        for (int h = 0; h < NH; h++) p[h] += __shfl_down_sync(0xffffffffu, p[h], o, 16);

    if (l == 0) {
        int src = ei[edge];
        int tgt = ei[n_edges + edge];
        float4 s1 = *(const float4*)&g_s1[src * NH];
        float4 s2 = *(const float4*)&g_s2[tgt * NH];
        float4 o4;
        float a0 = s1.x + s2.x + p[0];
        float a1 = s1.y + s2.y + p[1];
        float a2 = s1.z + s2.z + p[2];
        float a3 = s1.w + s2.w + p[3];
        o4.x = a0 > 0.f ? a0 : 0.2f * a0;
        o4.y = a1 > 0.f ? a1 : 0.2f * a1;
        o4.z = a2 > 0.f ? a2 : 0.2f * a2;
        o4.w = a3 > 0.f ? a3 : 0.2f * a3;
        *(float4*)&g_att[(size_t)edge * NH] = o4;
    }
}

// ---------------- fused softmax + aggregate (warp per node) ------------------
__global__ void kern_agg(const int* __restrict__ ei, float* __restrict__ out,
                         int n_nodes, int n_edges) {
    int node = blockIdx.x * 8 + (threadIdx.x >> 5);
    int lane = threadIdx.x & 31;
    if (node >= n_nodes) return;
    int beg = g_off[node], end = g_off[node + 1];
    int deg = end - beg;
    int head = lane >> 3;

    // pass A: per-head max over incident edges
    float4 mx = make_float4(-1e30f, -1e30f, -1e30f, -1e30f);
    for (int i = beg + lane; i < end; i += 32) {
        int e = g_csr[i];
        float4 v = *(const float4*)&g_att[(size_t)e * NH];
        mx.x = fmaxf(mx.x, v.x); mx.y = fmaxf(mx.y, v.y);
        mx.z = fmaxf(mx.z, v.z); mx.w = fmaxf(mx.w, v.w);
    }
#pragma unroll
    for (int o = 16; o; o >>= 1) {
        mx.x = fmaxf(mx.x, __shfl_xor_sync(0xffffffffu, mx.x, o));
        mx.y = fmaxf(mx.y, __shfl_xor_sync(0xffffffffu, mx.y, o));
        mx.z = fmaxf(mx.z, __shfl_xor_sync(0xffffffffu, mx.z, o));
        mx.w = fmaxf(mx.w, __shfl_xor_sync(0xffffffffu, mx.w, o));
    }
    float4 m = make_float4(fmaxf(mx.x, 0.f), fmaxf(mx.y, 0.f),
                           fmaxf(mx.z, 0.f), fmaxf(mx.w, 0.f));

    // pass B: sum of exp
    float4 s = make_float4(0.f, 0.f, 0.f, 0.f);
    for (int i = beg + lane; i < end; i += 32) {
        int e = g_csr[i];
        float4 v = *(const float4*)&g_att[(size_t)e * NH];
        s.x += __expf(v.x - m.x); s.y += __expf(v.y - m.y);
        s.z += __expf(v.z - m.z); s.w += __expf(v.w - m.w);
    }
#pragma unroll
    for (int o = 16; o; o >>= 1) {
        s.x += __shfl_xor_sync(0xffffffffu, s.x, o);
        s.y += __shfl_xor_sync(0xffffffffu, s.y, o);
        s.z += __shfl_xor_sync(0xffffffffu, s.z, o);
        s.w += __shfl_xor_sync(0xffffffffu, s.w, o);
    }
    float fE = (float)(n_edges - deg);
    float dx = s.x + fE * __expf(-m.x);
    float dy = s.y + fE * __expf(-m.y);
    float dz = s.z + fE * __expf(-m.z);
    float dw = s.w + fE * __expf(-m.w);
    float mh = (head == 0) ? m.x : (head == 1) ? m.y : (head == 2) ? m.z : m.w;
    float dh = (head == 0) ? dx : (head == 1) ? dy : (head == 2) ? dz : dw;
    float rd = 1.f / dh;

    // pass C: weighted gather-accumulate
    float4 acc = make_float4(0.f, 0.f, 0.f, 0.f);
    for (int base = beg; base < end; base += 32) {
        int cnt = min(32, end - base);
        int e = 0, src = 0;
        if (lane < cnt) {
            e = g_csr[base + lane];
            src = ei[e];
        }
        for (int j = 0; j < cnt; j++) {
            int ej = __shfl_sync(0xffffffffu, e, j);
            int sj = __shfl_sync(0xffffffffu, src, j);
            float av = __ldg(&g_att[(size_t)ej * NH + head]);
            float w = __expf(av - mh) * rd;
            float4 hv = *(const float4*)&g_h[(size_t)sj * ND + 4 * lane];
            acc.x += w * hv.x; acc.y += w * hv.y;
            acc.z += w * hv.z; acc.w += w * hv.w;
        }
    }
    *(float4*)&out[(size_t)node * ND + 4 * lane] = acc;
}

// ---------------- launch ------------------------------------------------------
extern "C" void kernel_launch(void* const* d_in, const int* in_sizes, int n_in,
                              void* d_out, int out_size) {
    const float* nodef = (const float*)d_in[0];
    const int* ei = (const int*)d_in[1];
    const float* edgef = (const float*)d_in[2];
    const float* W_node = (const float*)d_in[3];
    const float* W_edge = (const float*)d_in[4];
    const float* a = (const float*)d_in[5];
    float* out = (float*)d_out;

    int n_nodes = in_sizes[0] / ND;
    int n_edges = in_sizes[1] / 2;
    int nb = (n_nodes + 1023) >> 10;

    kern_v<<<1, 256>>>(W_edge, a);
    kern_zero_cnt<<<(n_nodes + 256) / 256, 256>>>(n_nodes);
    kern_hist<<<(n_edges + 255) / 256, 256>>>(ei, n_edges);
    kern_scan_part<<<nb, 256>>>(n_nodes);
    kern_scan_top<<<1, 64>>>(nb);
    kern_scan_add<<<(n_nodes + 255) / 256, 256>>>(n_nodes, n_edges);
    kern_scatter<<<(n_edges + 255) / 256, 256>>>(ei, n_edges);

    const int gemm_smem = (128 * 132 + 128 * 66) * (int)sizeof(float);  // ~99KB
    cudaFuncSetAttribute(kern_gemm, cudaFuncAttributeMaxDynamicSharedMemorySize,
                         gemm_smem);
    kern_gemm<<<(n_nodes + 63) / 64, 256, gemm_smem>>>(nodef, W_node, a, n_nodes);

    kern_p1<<<(n_edges + 15) / 16, 256>>>(edgef, ei, n_edges);
    kern_agg<<<(n_nodes + 7) / 8, 256>>>(ei, out, n_nodes, n_edges);
}